// round 16
// baseline (speedup 1.0000x reference)
#include <cuda_runtime.h>
#include <math.h>
#include <stdint.h>

#define B_  64
#define LQ  32
#define O_  128
#define LK  256
#define D_  128
#define FULLM 0xffffffffu
#define GRID_N 592          // exactly one wave at occupancy 4 on 148 SMs

// smem byte offsets (pitch 80B per 32-d chunk row, R15-verified layout)
#define KHI_O   0           // 256*80 = 20480
#define KLO_O   20480
#define QHI_O   40960       // 32*80 = 2560
#define QLO_O   43520
#define IVK_O   46080       // 256 f
#define IVQ_O   47104       // 32 f
#define WM_O    47232       // 256 f
#define PRED_O  48256       // 128 f
#define SMEM_REQ 48768

// Global scratch: chunk-major bf16 tiles + inverse norms (17.6MB, L2-resident)
__device__ uint2 g_khi[O_ * 4 * 256 * 8];   // ((o*4+c)*256+row)*8+e
__device__ uint2 g_klo[O_ * 4 * 256 * 8];
__device__ uint2 g_qhi[B_ * 4 * 32 * 8];    // ((b*4+c)*32+i)*8+e
__device__ uint2 g_qlo[B_ * 4 * 32 * 8];
__device__ float g_ivk[O_ * LK];
__device__ float g_ivq[B_ * LQ];
__device__ int   g_bar, g_depart;           // grid barrier (self-resetting)

__device__ __forceinline__ bool mask_at(const void* buf, int idx, int mode) {
    if (mode == 0) return ((const int*)buf)[idx] != 0;
    if (mode == 2) return ((const float*)buf)[idx] != 0.0f;
    return ((const unsigned char*)buf)[idx] != 0;
}
__device__ __forceinline__ uint32_t pack_bf(float lo, float hi) {
    uint32_t r;
    asm("cvt.rn.bf16x2.f32 %0, %1, %2;" : "=r"(r) : "f"(hi), "f"(lo));
    return r;
}
__device__ __forceinline__ void mma_bf16(float* d, uint32_t a0, uint32_t a1,
                                         uint32_t a2, uint32_t a3,
                                         uint32_t b0, uint32_t b1) {
    asm volatile(
        "mma.sync.aligned.m16n8k16.row.col.f32.bf16.bf16.f32 "
        "{%0,%1,%2,%3}, {%4,%5,%6,%7}, {%8,%9}, {%0,%1,%2,%3};"
        : "+f"(d[0]), "+f"(d[1]), "+f"(d[2]), "+f"(d[3])
        : "r"(a0), "r"(a1), "r"(a2), "r"(a3), "r"(b0), "r"(b1));
}

__global__ __launch_bounds__(128, 4)
void fused_score_kernel(const float* __restrict__ q,
                        const float* __restrict__ k,
                        const void* __restrict__ q_mask,
                        const void* __restrict__ k_mask,
                        const float* __restrict__ logit_scale,
                        float* __restrict__ out) {
    const int tid = threadIdx.x;
    const int w   = tid >> 5, l = tid & 31;
    const int g   = l >> 2, tg = l & 3;

    __shared__ int s_nact;
    __shared__ unsigned char s_blist[B_];
    __shared__ unsigned char s_act[B_];
    extern __shared__ char sb[];
    float* ivk_s = (float*)(sb + IVK_O);
    float* ivq_s = (float*)(sb + IVQ_O);
    float* wm    = (float*)(sb + WM_O);
    float* pred  = (float*)(sb + PRED_O);

    // ---- Phase A: dtype sniff + active flags + compact list ----
    int mode;
    {
        unsigned word = ((const unsigned*)q_mask)[l];
        unsigned bi = __ballot_sync(FULLM, word <= 1u);
        unsigned bf = __ballot_sync(FULLM, word == 0u || word == 0x3F800000u);
        mode = (bi == FULLM) ? 0 : (bf == FULLM) ? 2 : 1;
    }
    {
        int bb = tid >> 1, sub = tid & 1;
        int any = 0;
        #pragma unroll
        for (int e = 0; e < 16; e++)
            any |= mask_at(q_mask, bb * LQ + sub * 16 + e, mode) ? 1 : 0;
        any |= __shfl_xor_sync(FULLM, any, 1);
        if ((l & 1) == 0) s_act[bb] = (any == 0);
    }
    __syncthreads();
    if (w == 0) {
        unsigned f0 = __ballot_sync(FULLM, s_act[l] != 0);
        unsigned f1 = __ballot_sync(FULLM, s_act[32 + l] != 0);
        int n0 = __popc(f0);
        if (f0 & (1u << l)) s_blist[__popc(f0 & ((1u << l) - 1u))] = (unsigned char)l;
        if (f1 & (1u << l)) s_blist[n0 + __popc(f1 & ((1u << l) - 1u))] = (unsigned char)(32 + l);
        if (l == 0) s_nact = n0 + __popc(f1);
    }
    __syncthreads();
    if (blockIdx.x < B_ && !s_act[blockIdx.x])
        out[blockIdx.x * O_ + tid] = 0.0f;
    const int n_items = s_nact * O_;

    // ---- Phase 0: convert k/q to bf16 hi/lo in global scratch, norms ----
    const int gw = blockIdx.x * 4 + w;          // 0..2367
    if (n_items > 0) {
        for (int r = gw; r < O_ * LK; r += GRID_N * 4) {
            float4 v = ((const float4*)k)[r * 32 + l];
            float s = v.x*v.x + v.y*v.y + v.z*v.z + v.w*v.w;
            #pragma unroll
            for (int of = 16; of; of >>= 1) s += __shfl_xor_sync(FULLM, s, of);
            uint32_t h01 = pack_bf(v.x, v.y), h23 = pack_bf(v.z, v.w);
            float lx = v.x - __uint_as_float(h01 << 16);
            float ly = v.y - __uint_as_float(h01 & 0xFFFF0000u);
            float lz = v.z - __uint_as_float(h23 << 16);
            float lw = v.w - __uint_as_float(h23 & 0xFFFF0000u);
            uint32_t l01 = pack_bf(lx, ly), l23 = pack_bf(lz, lw);
            int o = r >> 8, ri = r & 255;
            size_t off = ((size_t)(o * 4 + (l >> 3)) * 256 + ri) * 8 + (l & 7);
            g_khi[off] = make_uint2(h01, h23);
            g_klo[off] = make_uint2(l01, l23);
            if (l == 0) g_ivk[r] = 1.0f / fmaxf(sqrtf(s), 1e-12f);
        }
        for (int r = gw; r < B_ * LQ; r += GRID_N * 4) {
            float4 v = ((const float4*)q)[r * 32 + l];
            float s = v.x*v.x + v.y*v.y + v.z*v.z + v.w*v.w;
            #pragma unroll
            for (int of = 16; of; of >>= 1) s += __shfl_xor_sync(FULLM, s, of);
            uint32_t h01 = pack_bf(v.x, v.y), h23 = pack_bf(v.z, v.w);
            float lx = v.x - __uint_as_float(h01 << 16);
            float ly = v.y - __uint_as_float(h01 & 0xFFFF0000u);
            float lz = v.z - __uint_as_float(h23 << 16);
            float lw = v.w - __uint_as_float(h23 & 0xFFFF0000u);
            uint32_t l01 = pack_bf(lx, ly), l23 = pack_bf(lz, lw);
            int bq = r >> 5, i = r & 31;
            size_t off = ((size_t)(bq * 4 + (l >> 3)) * 32 + i) * 8 + (l & 7);
            g_qhi[off] = make_uint2(h01, h23);
            g_qlo[off] = make_uint2(l01, l23);
            if (l == 0) g_ivq[r] = 1.0f / fmaxf(sqrtf(s), 1e-12f);
        }
    }

    // ---- grid barrier (all 592 blocks co-resident by construction) ----
    if (tid == 0) {
        __threadfence();
        atomicAdd(&g_bar, 1);
        while (*(volatile int*)&g_bar < GRID_N) { }
        __threadfence();
    }
    __syncthreads();

    // ---- Phase 1: items = (active b, o); pure copy + MMA + epilogue ----
    for (int item = blockIdx.x; item < n_items; item += GRID_N) {
        const int b = s_blist[item >> 7];
        const int o = item & (O_ - 1);

        __syncthreads();                 // prev epilogue done with smem
        wm[tid]       = mask_at(k_mask, o * LK + tid, mode) ? 0.0f : 1.0f;
        wm[128 + tid] = mask_at(k_mask, o * LK + 128 + tid, mode) ? 0.0f : 1.0f;
        ivk_s[tid]       = g_ivk[o * LK + tid];
        ivk_s[128 + tid] = g_ivk[o * LK + 128 + tid];
        if (tid < 32) ivq_s[tid] = g_ivq[b * LQ + tid];

        float acc[4][4][4];
        #pragma unroll
        for (int mt = 0; mt < 4; mt++)
            #pragma unroll
            for (int nt = 0; nt < 4; nt++)
                #pragma unroll
                for (int e = 0; e < 4; e++) acc[mt][nt][e] = 0.0f;

        #pragma unroll 1
        for (int c = 0; c < 4; c++) {
            __syncthreads();             // prev chunk's mma done with smem
            // flat copy: global dense 64B rows -> smem pitch-80 rows
            {
                const uint4* sh = (const uint4*)(g_khi + (size_t)(o * 4 + c) * 256 * 8);
                const uint4* sl = (const uint4*)(g_klo + (size_t)(o * 4 + c) * 256 * 8);
                #pragma unroll
                for (int it = 0; it < 8; it++) {
                    int idx = it * 128 + tid;
                    int row = idx >> 2, qd = idx & 3;
                    *(uint4*)(sb + KHI_O + row * 80 + qd * 16) = sh[idx];
                    *(uint4*)(sb + KLO_O + row * 80 + qd * 16) = sl[idx];
                }
                const uint4* qh = (const uint4*)(g_qhi + (size_t)(b * 4 + c) * 32 * 8);
                const uint4* ql = (const uint4*)(g_qlo + (size_t)(b * 4 + c) * 32 * 8);
                int row = tid >> 2, qd = tid & 3;
                *(uint4*)(sb + QHI_O + row * 80 + qd * 16) = qh[tid];
                *(uint4*)(sb + QLO_O + row * 80 + qd * 16) = ql[tid];
            }
            __syncthreads();

            // ---- MMA phase (identical to R15) ----
            #pragma unroll
            for (int kh = 0; kh < 2; kh++) {
                uint32_t bh[4][2], bl[4][2];
                #pragma unroll
                for (int nt = 0; nt < 4; nt++) {
                    int qb = (nt * 8 + g) * 80 + (kh * 16 + 2 * tg) * 2;
                    bh[nt][0] = *(const uint32_t*)(sb + QHI_O + qb);
                    bh[nt][1] = *(const uint32_t*)(sb + QHI_O + qb + 16);
                    bl[nt][0] = *(const uint32_t*)(sb + QLO_O + qb);
                    bl[nt][1] = *(const uint32_t*)(sb + QLO_O + qb + 16);
                }
                #pragma unroll
                for (int mt = 0; mt < 4; mt++) {
                    int r0 = w * 64 + mt * 16 + g;
                    int ab = r0 * 80 + (kh * 16 + 2 * tg) * 2;
                    uint32_t ah0 = *(const uint32_t*)(sb + KHI_O + ab);
                    uint32_t ah1 = *(const uint32_t*)(sb + KHI_O + ab + 8 * 80);
                    uint32_t ah2 = *(const uint32_t*)(sb + KHI_O + ab + 16);
                    uint32_t ah3 = *(const uint32_t*)(sb + KHI_O + ab + 8 * 80 + 16);
                    uint32_t al0 = *(const uint32_t*)(sb + KLO_O + ab);
                    uint32_t al1 = *(const uint32_t*)(sb + KLO_O + ab + 8 * 80);
                    uint32_t al2 = *(const uint32_t*)(sb + KLO_O + ab + 16);
                    uint32_t al3 = *(const uint32_t*)(sb + KLO_O + ab + 8 * 80 + 16);
                    #pragma unroll
                    for (int nt = 0; nt < 4; nt++) {
                        mma_bf16(acc[mt][nt], ah0, ah1, ah2, ah3, bh[nt][0], bh[nt][1]);
                        mma_bf16(acc[mt][nt], ah0, ah1, ah2, ah3, bl[nt][0], bl[nt][1]);
                        mma_bf16(acc[mt][nt], al0, al1, al2, al3, bh[nt][0], bh[nt][1]);
                    }
                }
            }
        }

        // ---- epilogue (R15 pattern; norms from scratch) ----
        __syncthreads();
        float wj[8], kj[8];
        #pragma unroll
        for (int mt = 0; mt < 4; mt++) {
            int j0 = w * 64 + mt * 16 + g;
            wj[2 * mt]     = wm[j0];     kj[2 * mt]     = 12.0f * ivk_s[j0];
            wj[2 * mt + 1] = wm[j0 + 8]; kj[2 * mt + 1] = 12.0f * ivk_s[j0 + 8];
        }
        #pragma unroll
        for (int nt = 0; nt < 4; nt++) {
            int i0 = nt * 8 + 2 * tg;
            float q0 = ivq_s[i0], q1 = ivq_s[i0 + 1];
            float s0 = 0.0f, s1 = 0.0f;
            #pragma unroll
            for (int mt = 0; mt < 4; mt++) {
                s0 += wj[2*mt]   * __expf(kj[2*mt]   * q0 * acc[mt][nt][0])
                    + wj[2*mt+1] * __expf(kj[2*mt+1] * q0 * acc[mt][nt][2]);
                s1 += wj[2*mt]   * __expf(kj[2*mt]   * q1 * acc[mt][nt][1])
                    + wj[2*mt+1] * __expf(kj[2*mt+1] * q1 * acc[mt][nt][3]);
            }
            #pragma unroll
            for (int of = 4; of < 32; of <<= 1) {
                s0 += __shfl_xor_sync(FULLM, s0, of);
                s1 += __shfl_xor_sync(FULLM, s1, of);
            }
            if (g == 0) {
                pred[w * 32 + i0]     = s0;
                pred[w * 32 + i0 + 1] = s1;
            }
        }
        __syncthreads();
        if (w == 0) {
            float p = pred[l] + pred[32 + l] + pred[64 + l] + pred[96 + l];
            float lse = __logf(p);               // -inf if all j masked
            #pragma unroll
            for (int of = 16; of; of >>= 1) lse += __shfl_xor_sync(FULLM, lse, of);
            if (l == 0) {
                float s = lse * (1.0f / 12.0f);
                s = s / (sqrtf((float)(LQ * LK)) + 1e-6f);
                s *= fminf(expf(logit_scale[0]), 100.0f);
                if (!isfinite(s)) s = 0.0f;
                out[b * O_ + o] = s;
            }
        }
    }

    // ---- departure: last block resets barrier state for graph replay ----
    __syncthreads();
    if (tid == 0) {
        __threadfence();
        int d = atomicAdd(&g_depart, 1);
        if (d == GRID_N - 1) {
            g_bar = 0;
            g_depart = 0;
            __threadfence();
        }
    }
}

// ---------------------------------------------------------------------------
extern "C" void kernel_launch(void* const* d_in, const int* in_sizes, int n_in,
                              void* d_out, int out_size) {
    const float* q  = (const float*)d_in[0];
    const float* k  = (const float*)d_in[1];
    const void*  qm = d_in[2];
    const void*  km = d_in[3];
    const float* ls = (const float*)d_in[4];
    float* out = (float*)d_out;

    cudaFuncSetAttribute(fused_score_kernel,
                         cudaFuncAttributeMaxDynamicSharedMemorySize, SMEM_REQ);
    fused_score_kernel<<<GRID_N, 128, SMEM_REQ>>>(q, k, qm, km, ls, out);
}

// round 17
// speedup vs baseline: 2.2353x; 2.2353x over previous
#include <cuda_runtime.h>
#include <math.h>
#include <stdint.h>

#define B_  64
#define LQ  32
#define O_  128
#define LK  256
#define D_  128
#define FULLM 0xffffffffu

// smem byte offsets; k/q rows pitch 272B (128 d x 2B bf16 + 16B pad)
#define KHI 0            // 256*272 = 69632
#define KLO 69632
#define QHI 139264       // 32*272 = 8704
#define QLO 147968
#define IVK 156672       // 256 f
#define IVQ 157696       // 32 f
#define WMO 157824       // 256 f
#define PRD 158848       // 256 f
#define SMEM_REQ 159872

__device__ __forceinline__ bool mask_at(const void* buf, int idx, int mode) {
    if (mode == 0) return ((const int*)buf)[idx] != 0;
    if (mode == 2) return ((const float*)buf)[idx] != 0.0f;
    return ((const unsigned char*)buf)[idx] != 0;
}
__device__ __forceinline__ uint32_t pack_bf(float lo, float hi) {
    uint32_t r;
    asm("cvt.rn.bf16x2.f32 %0, %1, %2;" : "=r"(r) : "f"(hi), "f"(lo));
    return r;
}
__device__ __forceinline__ void mma_bf16(float* d, uint32_t a0, uint32_t a1,
                                         uint32_t a2, uint32_t a3,
                                         uint32_t b0, uint32_t b1) {
    asm volatile(
        "mma.sync.aligned.m16n8k16.row.col.f32.bf16.bf16.f32 "
        "{%0,%1,%2,%3}, {%4,%5,%6,%7}, {%8,%9}, {%0,%1,%2,%3};"
        : "+f"(d[0]), "+f"(d[1]), "+f"(d[2]), "+f"(d[3])
        : "r"(a0), "r"(a1), "r"(a2), "r"(a3), "r"(b0), "r"(b1));
}
// reconstruct fp32 pair from hi/lo bf16x2 words, accumulate squares
__device__ __forceinline__ void acc_ssq(uint32_t h, uint32_t lo, float& s) {
    float v0 = __uint_as_float(h << 16)          + __uint_as_float(lo << 16);
    float v1 = __uint_as_float(h & 0xFFFF0000u)  + __uint_as_float(lo & 0xFFFF0000u);
    s = fmaf(v0, v0, s); s = fmaf(v1, v1, s);
}

// ---------------------------------------------------------------------------
// Grid 128 (block = o), 256 threads, occ 1 (~156KB smem).
// Phase A: sniff + active-batch list + inactive-row zeroing.
// Phase B: convert k[o] ONCE to resident bf16 hi/lo smem; norms post-hoc.
// Phase C: per active b: stage q (resident), then sync-free MMA sweep over
//          all 4 K-chunks (R15-verified fragment maps, pitch 272, +c*64),
//          3-term split (HiHi+HiLo+LoHi), epilogue lse -> out[b,o].
// ---------------------------------------------------------------------------
__global__ __launch_bounds__(256, 1)
void fused_score_kernel(const float* __restrict__ q,
                        const float* __restrict__ k,
                        const void* __restrict__ q_mask,
                        const void* __restrict__ k_mask,
                        const float* __restrict__ logit_scale,
                        float* __restrict__ out) {
    const int tid = threadIdx.x;
    const int w   = tid >> 5, l = tid & 31;
    const int g   = l >> 2, tg = l & 3;
    const int o   = blockIdx.x;

    __shared__ int s_nact;
    __shared__ unsigned char s_blist[B_];
    __shared__ unsigned char s_act[B_];
    extern __shared__ char sb[];
    float* ivk_s = (float*)(sb + IVK);
    float* ivq_s = (float*)(sb + IVQ);
    float* wm    = (float*)(sb + WMO);
    float* pred  = (float*)(sb + PRD);

    // ---- Phase A ----
    int mode;
    {
        unsigned word = ((const unsigned*)q_mask)[l];
        unsigned bi = __ballot_sync(FULLM, word <= 1u);
        unsigned bf = __ballot_sync(FULLM, word == 0u || word == 0x3F800000u);
        mode = (bi == FULLM) ? 0 : (bf == FULLM) ? 2 : 1;
    }
    {
        int bb = tid >> 2, sub = tid & 3;
        int any = 0;
        #pragma unroll
        for (int e = 0; e < 8; e++)
            any |= mask_at(q_mask, bb * LQ + sub * 8 + e, mode) ? 1 : 0;
        any |= __shfl_xor_sync(FULLM, any, 1);
        any |= __shfl_xor_sync(FULLM, any, 2);
        if ((l & 3) == 0) s_act[bb] = (any == 0);
    }
    __syncthreads();
    if (w == 0) {
        unsigned f0 = __ballot_sync(FULLM, s_act[l] != 0);
        unsigned f1 = __ballot_sync(FULLM, s_act[32 + l] != 0);
        int n0 = __popc(f0);
        if (f0 & (1u << l)) s_blist[__popc(f0 & ((1u << l) - 1u))] = (unsigned char)l;
        if (f1 & (1u << l)) s_blist[n0 + __popc(f1 & ((1u << l) - 1u))] = (unsigned char)(32 + l);
        if (l == 0) s_nact = n0 + __popc(f1);
    }
    __syncthreads();
    if (o < B_ && !s_act[o] && tid < O_)
        out[o * O_ + tid] = 0.0f;                   // zero inactive batch row
    const int nact = s_nact;
    if (nact == 0) return;

    // ---- Phase B: convert k[o] once (256 rows x 128 d), then norms ----
    wm[tid] = mask_at(k_mask, o * LK + tid, mode) ? 0.0f : 1.0f;
    {
        const float4* kr4 = (const float4*)(k + (size_t)o * LK * D_);
        #pragma unroll
        for (int it = 0; it < 32; it++) {
            int idx = it * 256 + tid;               // 8192 float4
            int row = idx >> 5, f4i = idx & 31;
            float4 v = kr4[idx];
            uint32_t h01 = pack_bf(v.x, v.y), h23 = pack_bf(v.z, v.w);
            float lx = v.x - __uint_as_float(h01 << 16);
            float ly = v.y - __uint_as_float(h01 & 0xFFFF0000u);
            float lz = v.z - __uint_as_float(h23 << 16);
            float lw = v.w - __uint_as_float(h23 & 0xFFFF0000u);
            uint32_t l01 = pack_bf(lx, ly), l23 = pack_bf(lz, lw);
            int byo = row * 272 + f4i * 8;
            *(uint2*)(sb + KHI + byo) = make_uint2(h01, h23);
            *(uint2*)(sb + KLO + byo) = make_uint2(l01, l23);
        }
    }
    __syncthreads();
    {   // k norms: thread tid owns row tid (hi+lo reconstruction, err 2^-17)
        const uint2* rh = (const uint2*)(sb + KHI + tid * 272);
        const uint2* rl = (const uint2*)(sb + KLO + tid * 272);
        float s = 0.0f;
        #pragma unroll
        for (int j = 0; j < 32; j++) {
            uint2 h = rh[j], lo = rl[j];
            acc_ssq(h.x, lo.x, s);
            acc_ssq(h.y, lo.y, s);
        }
        ivk_s[tid] = 1.0f / fmaxf(sqrtf(s), 1e-12f);
    }

    // ---- Phase C: loop over active batches ----
    for (int bi = 0; bi < nact; bi++) {
        const int b = s_blist[bi];

        __syncthreads();                 // prev epilogue / norms done
        {   // stage q[b]: 1024 float4
            const float4* qr4 = (const float4*)(q + (size_t)b * LQ * D_);
            #pragma unroll
            for (int it = 0; it < 4; it++) {
                int idx = it * 256 + tid;
                int row = idx >> 5, f4i = idx & 31;
                float4 v = qr4[idx];
                uint32_t h01 = pack_bf(v.x, v.y), h23 = pack_bf(v.z, v.w);
                float lx = v.x - __uint_as_float(h01 << 16);
                float ly = v.y - __uint_as_float(h01 & 0xFFFF0000u);
                float lz = v.z - __uint_as_float(h23 << 16);
                float lw = v.w - __uint_as_float(h23 & 0xFFFF0000u);
                uint32_t l01 = pack_bf(lx, ly), l23 = pack_bf(lz, lw);
                int byo = row * 272 + f4i * 8;
                *(uint2*)(sb + QHI + byo) = make_uint2(h01, h23);
                *(uint2*)(sb + QLO + byo) = make_uint2(l01, l23);
            }
        }
        __syncthreads();
        if (tid < 32) {                  // q norms (warp 0)
            const uint2* rh = (const uint2*)(sb + QHI + tid * 272);
            const uint2* rl = (const uint2*)(sb + QLO + tid * 272);
            float s = 0.0f;
            #pragma unroll
            for (int j = 0; j < 32; j++) {
                uint2 h = rh[j], lo = rl[j];
                acc_ssq(h.x, lo.x, s);
                acc_ssq(h.y, lo.y, s);
            }
            ivq_s[tid] = 1.0f / fmaxf(sqrtf(s), 1e-12f);
        }
        __syncthreads();

        // ---- MMA sweep: warp w owns j [w*32, +32) (2 m16 tiles) x 32 i ----
        float acc[2][4][4];
        #pragma unroll
        for (int mt = 0; mt < 2; mt++)
            #pragma unroll
            for (int nt = 0; nt < 4; nt++)
                #pragma unroll
                for (int e = 0; e < 4; e++) acc[mt][nt][e] = 0.0f;

        #pragma unroll
        for (int c = 0; c < 4; c++) {
            #pragma unroll
            for (int kh = 0; kh < 2; kh++) {
                const int fo = c * 64 + (kh * 16 + 2 * tg) * 2;
                uint32_t bh[4][2], bl[4][2];
                #pragma unroll
                for (int nt = 0; nt < 4; nt++) {
                    int qb = (nt * 8 + g) * 272 + fo;
                    bh[nt][0] = *(const uint32_t*)(sb + QHI + qb);
                    bh[nt][1] = *(const uint32_t*)(sb + QHI + qb + 16);
                    bl[nt][0] = *(const uint32_t*)(sb + QLO + qb);
                    bl[nt][1] = *(const uint32_t*)(sb + QLO + qb + 16);
                }
                #pragma unroll
                for (int mt = 0; mt < 2; mt++) {
                    int ab = (w * 32 + mt * 16 + g) * 272 + fo;
                    uint32_t ah0 = *(const uint32_t*)(sb + KHI + ab);
                    uint32_t ah1 = *(const uint32_t*)(sb + KHI + ab + 8 * 272);
                    uint32_t ah2 = *(const uint32_t*)(sb + KHI + ab + 16);
                    uint32_t ah3 = *(const uint32_t*)(sb + KHI + ab + 8 * 272 + 16);
                    uint32_t al0 = *(const uint32_t*)(sb + KLO + ab);
                    uint32_t al1 = *(const uint32_t*)(sb + KLO + ab + 8 * 272);
                    uint32_t al2 = *(const uint32_t*)(sb + KLO + ab + 16);
                    uint32_t al3 = *(const uint32_t*)(sb + KLO + ab + 8 * 272 + 16);
                    #pragma unroll
                    for (int nt = 0; nt < 4; nt++) {
                        mma_bf16(acc[mt][nt], ah0, ah1, ah2, ah3, bh[nt][0], bh[nt][1]);
                        mma_bf16(acc[mt][nt], ah0, ah1, ah2, ah3, bl[nt][0], bl[nt][1]);
                        mma_bf16(acc[mt][nt], al0, al1, al2, al3, bh[nt][0], bh[nt][1]);
                    }
                }
            }
        }

        // ---- epilogue ----
        float wj[4], kj[4];
        #pragma unroll
        for (int mt = 0; mt < 2; mt++) {
            int j0 = w * 32 + mt * 16 + g;
            wj[2 * mt]     = wm[j0];     kj[2 * mt]     = 12.0f * ivk_s[j0];
            wj[2 * mt + 1] = wm[j0 + 8]; kj[2 * mt + 1] = 12.0f * ivk_s[j0 + 8];
        }
        #pragma unroll
        for (int nt = 0; nt < 4; nt++) {
            int i0 = nt * 8 + 2 * tg;
            float q0 = ivq_s[i0], q1 = ivq_s[i0 + 1];
            float s0 = 0.0f, s1 = 0.0f;
            #pragma unroll
            for (int mt = 0; mt < 2; mt++) {
                s0 += wj[2*mt]   * __expf(kj[2*mt]   * q0 * acc[mt][nt][0])
                    + wj[2*mt+1] * __expf(kj[2*mt+1] * q0 * acc[mt][nt][2]);
                s1 += wj[2*mt]   * __expf(kj[2*mt]   * q1 * acc[mt][nt][1])
                    + wj[2*mt+1] * __expf(kj[2*mt+1] * q1 * acc[mt][nt][3]);
            }
            #pragma unroll
            for (int of = 4; of < 32; of <<= 1) {
                s0 += __shfl_xor_sync(FULLM, s0, of);
                s1 += __shfl_xor_sync(FULLM, s1, of);
            }
            if (g == 0) {
                pred[w * 32 + i0]     = s0;
                pred[w * 32 + i0 + 1] = s1;
            }
        }
        __syncthreads();
        if (w == 0) {
            float p = 0.0f;
            #pragma unroll
            for (int ww = 0; ww < 8; ww++) p += pred[ww * 32 + l];
            float lse = __logf(p);               // -inf if all j masked
            #pragma unroll
            for (int of = 16; of; of >>= 1) lse += __shfl_xor_sync(FULLM, lse, of);
            if (l == 0) {
                float s = lse * (1.0f / 12.0f);
                s = s / (sqrtf((float)(LQ * LK)) + 1e-6f);
                s *= fminf(expf(logit_scale[0]), 100.0f);
                if (!isfinite(s)) s = 0.0f;
                out[b * O_ + o] = s;
            }
        }
    }
}

// ---------------------------------------------------------------------------
extern "C" void kernel_launch(void* const* d_in, const int* in_sizes, int n_in,
                              void* d_out, int out_size) {
    const float* q  = (const float*)d_in[0];
    const float* k  = (const float*)d_in[1];
    const void*  qm = d_in[2];
    const void*  km = d_in[3];
    const float* ls = (const float*)d_in[4];
    float* out = (float*)d_out;

    cudaFuncSetAttribute(fused_score_kernel,
                         cudaFuncAttributeMaxDynamicSharedMemorySize, SMEM_REQ);
    fused_score_kernel<<<O_, 256, SMEM_REQ>>>(q, k, qm, km, ls, out);
}